// round 2
// baseline (speedup 1.0000x reference)
#include <cuda_runtime.h>
#include <math.h>

#define BB 4
#define CC 256
#define NN 4096

// Scratch: token-major projections [B][N][C]
static __device__ float g_Q[BB * NN * CC];
static __device__ float g_K[BB * NN * CC];   // k + pos folded in
static __device__ float g_V[BB * NN * CC];

// XOR swizzle for [row][64-col] smem tiles: permutes float4-groups within a row
// so that column-strided (transposed) scalar writes spread across banks while
// float4 reads of 4 consecutive cols stay contiguous & 16B aligned.
__device__ __forceinline__ int swz(int row, int col) {
    return row * 64 + ((((col >> 2) ^ ((row >> 2) & 15))) << 2) + (col & 3);
}
__device__ __forceinline__ int swz4(int row, int g4) {
    return row * 64 + (((g4) ^ ((row >> 2) & 15)) << 2);
}

// ---------------------------------------------------------------------------
// Projection kernel: out[b][n][o] = sum_c W[o][c] * x[b][c][n] + bias[o] (+pos)
// grid: (N/64, C/64, B*3); block: 256 threads; each thread: 4x4 of a 64x64 tile
// ---------------------------------------------------------------------------
__global__ __launch_bounds__(256) void proj_kernel(
    const float* __restrict__ x,
    const float* __restrict__ Wq, const float* __restrict__ bq,
    const float* __restrict__ Wk, const float* __restrict__ bk,
    const float* __restrict__ Wv, const float* __restrict__ bv,
    const float* __restrict__ rel_h, const float* __restrict__ rel_w)
{
    __shared__ float Xs[16][64];   // [c_local][token]
    __shared__ float Ws[16][68];   // [c_local][o], padded rows (272B, 16B-aligned)

    const int tid = threadIdx.x;
    const int ty = tid >> 4, tx = tid & 15;
    const int n0 = blockIdx.x * 64;
    const int o0 = blockIdx.y * 64;
    const int b = blockIdx.z / 3;
    const int which = blockIdx.z % 3;

    const float* Wm   = (which == 0) ? Wq : (which == 1) ? Wk : Wv;
    const float* bias = (which == 0) ? bq : (which == 1) ? bk : bv;
    float* outp       = (which == 0) ? g_Q : (which == 1) ? g_K : g_V;

    const float* xb = x + (size_t)b * CC * NN;

    const int lcl = tid >> 4, lnf = tid & 15;  // Xs load mapping
    const int lo  = tid >> 2, lcf = tid & 3;   // Ws load mapping

    float acc[4][4] = {};

    for (int c0 = 0; c0 < CC; c0 += 16) {
        float4 xv = *(const float4*)&xb[(size_t)(c0 + lcl) * NN + n0 + lnf * 4];
        float4 wv = *(const float4*)&Wm[(o0 + lo) * CC + c0 + lcf * 4];
        *(float4*)&Xs[lcl][lnf * 4] = xv;
        Ws[lcf * 4 + 0][lo] = wv.x;
        Ws[lcf * 4 + 1][lo] = wv.y;
        Ws[lcf * 4 + 2][lo] = wv.z;
        Ws[lcf * 4 + 3][lo] = wv.w;
        __syncthreads();
        #pragma unroll
        for (int kk = 0; kk < 16; kk++) {
            float4 a4 = *(const float4*)&Xs[kk][ty * 4];
            float4 w4 = *(const float4*)&Ws[kk][tx * 4];
            float a[4] = {a4.x, a4.y, a4.z, a4.w};
            float w[4] = {w4.x, w4.y, w4.z, w4.w};
            #pragma unroll
            for (int i = 0; i < 4; i++)
                #pragma unroll
                for (int j = 0; j < 4; j++)
                    acc[i][j] += a[i] * w[j];
        }
        __syncthreads();
    }

    float bs[4];
    #pragma unroll
    for (int j = 0; j < 4; j++) bs[j] = bias[o0 + tx * 4 + j];

    #pragma unroll
    for (int i = 0; i < 4; i++) {
        int n = n0 + ty * 4 + i;
        float r[4];
        #pragma unroll
        for (int j = 0; j < 4; j++) {
            r[j] = acc[i][j] + bs[j];
            if (which == 1) {
                // pos[c, n] = rel_h[c, n/W] + rel_w[c, n%W], W=H=64
                int c = o0 + tx * 4 + j;
                r[j] += rel_h[c * 64 + (n >> 6)] + rel_w[c * 64 + (n & 63)];
            }
        }
        float4 st = {r[0], r[1], r[2], r[3]};
        *(float4*)&outp[((size_t)b * NN + n) * CC + o0 + tx * 4] = st;
    }
}

// ---------------------------------------------------------------------------
// Flash attention (fp32 SIMT) + residual epilogue.
// grid: (N/64, B); block 256 (16x16 thread tiles).
// Per block: 64 queries, loop over 64 key tiles of 64.
// smem: Qs[256][64] swz | Ks[256][64] swz | Vs[64][256] | Ps[64][64] swz
// ---------------------------------------------------------------------------
__global__ __launch_bounds__(256, 1) void attn_kernel(
    const float* __restrict__ x,
    const float* __restrict__ gamma,
    float* __restrict__ out)
{
    extern __shared__ float sm[];
    float* Qs = sm;              // 16384 floats (transposed, swizzled)
    float* Ks = sm + 16384;      // 16384
    float* Vs = sm + 32768;      // 16384, direct [n][d]
    float* Ps = sm + 49152;      // 4096, [key][row] swizzled

    const int tid = threadIdx.x;
    const int ty = tid >> 4, tx = tid & 15;
    const int m0 = blockIdx.x * 64;
    const int b  = blockIdx.y;

    const float* Qg = g_Q + ((size_t)b * NN + m0) * CC;
    const float* Kg = g_K + (size_t)b * NN * CC;
    const float* Vg = g_V + (size_t)b * NN * CC;

    const int ltok = tid >> 6;   // 0..3
    const int lcf  = tid & 63;   // 0..63

    // Load Q tile transposed into Qs[c][token]
    #pragma unroll
    for (int p = 0; p < 16; p++) {
        int tok = ltok + p * 4;
        float4 v = *(const float4*)&Qg[tok * CC + lcf * 4];
        Qs[swz(lcf * 4 + 0, tok)] = v.x;
        Qs[swz(lcf * 4 + 1, tok)] = v.y;
        Qs[swz(lcf * 4 + 2, tok)] = v.z;
        Qs[swz(lcf * 4 + 3, tok)] = v.w;
    }

    // O accumulator: rows ty*4+i, cols d = 64*j + tx*4 + q  -> o[i][j*4+q]
    float o[4][16];
    #pragma unroll
    for (int i = 0; i < 4; i++)
        #pragma unroll
        for (int j = 0; j < 16; j++) o[i][j] = 0.0f;
    float mrow[4] = {-INFINITY, -INFINITY, -INFINITY, -INFINITY};
    float lrow[4] = {0.0f, 0.0f, 0.0f, 0.0f};

    for (int nt = 0; nt < 64; nt++) {
        const float* Kt = Kg + (size_t)nt * 64 * CC;
        const float* Vt = Vg + (size_t)nt * 64 * CC;

        __syncthreads();   // previous PV done (and Q load on first iter)
        #pragma unroll
        for (int p = 0; p < 16; p++) {
            int tok = ltok + p * 4;
            float4 kv = *(const float4*)&Kt[tok * CC + lcf * 4];
            Ks[swz(lcf * 4 + 0, tok)] = kv.x;
            Ks[swz(lcf * 4 + 1, tok)] = kv.y;
            Ks[swz(lcf * 4 + 2, tok)] = kv.z;
            Ks[swz(lcf * 4 + 3, tok)] = kv.w;
            float4 vv = *(const float4*)&Vt[tok * CC + lcf * 4];
            *(float4*)&Vs[tok * CC + lcf * 4] = vv;
        }
        __syncthreads();

        // S[4][4] = Q(rows ty*4..) . K(cols tx*4..) over 256 dims
        float s[4][4] = {};
        #pragma unroll 8
        for (int kk = 0; kk < CC; kk++) {
            float4 q4 = *(const float4*)&Qs[swz4(kk, ty)];
            float4 k4 = *(const float4*)&Ks[swz4(kk, tx)];
            float q[4] = {q4.x, q4.y, q4.z, q4.w};
            float k[4] = {k4.x, k4.y, k4.z, k4.w};
            #pragma unroll
            for (int i = 0; i < 4; i++)
                #pragma unroll
                for (int j = 0; j < 4; j++)
                    s[i][j] += q[i] * k[j];
        }

        // Online softmax (row stats across the 16 tx lanes)
        #pragma unroll
        for (int i = 0; i < 4; i++) {
            float rm = fmaxf(fmaxf(s[i][0], s[i][1]), fmaxf(s[i][2], s[i][3]));
            #pragma unroll
            for (int off = 1; off < 16; off <<= 1)
                rm = fmaxf(rm, __shfl_xor_sync(0xffffffffu, rm, off));
            float mnew = fmaxf(mrow[i], rm);
            float p0 = __expf(s[i][0] - mnew);
            float p1 = __expf(s[i][1] - mnew);
            float p2 = __expf(s[i][2] - mnew);
            float p3 = __expf(s[i][3] - mnew);
            float rs = (p0 + p1) + (p2 + p3);
            #pragma unroll
            for (int off = 1; off < 16; off <<= 1)
                rs += __shfl_xor_sync(0xffffffffu, rs, off);
            float scale = __expf(mrow[i] - mnew);
            lrow[i] = lrow[i] * scale + rs;
            if (scale != 1.0f) {
                #pragma unroll
                for (int j = 0; j < 16; j++) o[i][j] *= scale;
            }
            mrow[i] = mnew;
            int r = ty * 4 + i;
            Ps[swz(tx * 4 + 0, r)] = p0;
            Ps[swz(tx * 4 + 1, r)] = p1;
            Ps[swz(tx * 4 + 2, r)] = p2;
            Ps[swz(tx * 4 + 3, r)] = p3;
        }
        __syncthreads();

        // O += P @ V
        #pragma unroll 2
        for (int n = 0; n < 64; n++) {
            float4 p4 = *(const float4*)&Ps[swz4(n, ty)];
            float pr[4] = {p4.x, p4.y, p4.z, p4.w};
            #pragma unroll
            for (int j = 0; j < 4; j++) {
                float4 v4 = *(const float4*)&Vs[n * CC + 64 * j + tx * 4];
                float vv[4] = {v4.x, v4.y, v4.z, v4.w};
                #pragma unroll
                for (int i = 0; i < 4; i++) {
                    o[i][j * 4 + 0] += pr[i] * vv[0];
                    o[i][j * 4 + 1] += pr[i] * vv[1];
                    o[i][j * 4 + 2] += pr[i] * vv[2];
                    o[i][j * 4 + 3] += pr[i] * vv[3];
                }
            }
        }
    }

    float inv[4];
    #pragma unroll
    for (int i = 0; i < 4; i++) inv[i] = 1.0f / lrow[i];

    // Stage O transposed [d][token] in smem (reuse Qs) for coalesced output
    __syncthreads();
    float* Os = Qs;
    #pragma unroll
    for (int j = 0; j < 4; j++)
        #pragma unroll
        for (int q = 0; q < 4; q++) {
            int d = 64 * j + tx * 4 + q;
            #pragma unroll
            for (int i = 0; i < 4; i++)
                Os[swz(d, ty * 4 + i)] = o[i][j * 4 + q] * inv[i];
        }
    __syncthreads();

    const float g = gamma[0];
    const int ed  = tid >> 4;   // 0..15
    const int et4 = tid & 15;   // token float4 group
    #pragma unroll
    for (int p = 0; p < 16; p++) {
        int d = ed + p * 16;
        float4 ov = *(const float4*)&Os[swz4(d, et4)];
        size_t gi = ((size_t)b * CC + d) * NN + m0 + et4 * 4;
        float4 xv = *(const float4*)&x[gi];
        float4 r = {g * ov.x + xv.x, g * ov.y + xv.y,
                    g * ov.z + xv.z, g * ov.w + xv.w};
        *(float4*)&out[gi] = r;
    }
}

// ---------------------------------------------------------------------------
extern "C" void kernel_launch(void* const* d_in, const int* in_sizes, int n_in,
                              void* d_out, int out_size)
{
    (void)in_sizes; (void)n_in; (void)out_size;
    const float* x     = (const float*)d_in[0];
    const float* Wq    = (const float*)d_in[1];
    const float* bq    = (const float*)d_in[2];
    const float* Wk    = (const float*)d_in[3];
    const float* bk    = (const float*)d_in[4];
    const float* Wv    = (const float*)d_in[5];
    const float* bv    = (const float*)d_in[6];
    const float* rel_h = (const float*)d_in[7];
    const float* rel_w = (const float*)d_in[8];
    const float* gamma = (const float*)d_in[9];
    float* out = (float*)d_out;

    const int smem_bytes = 53248 * 4;   // 208 KB
    cudaFuncSetAttribute(attn_kernel,
                         cudaFuncAttributeMaxDynamicSharedMemorySize, smem_bytes);

    proj_kernel<<<dim3(64, 4, 12), 256>>>(x, Wq, bq, Wk, bk, Wv, bv, rel_h, rel_w);
    attn_kernel<<<dim3(64, 4), 256, smem_bytes>>>(x, gamma, out);
}